// round 17
// baseline (speedup 1.0000x reference)
#include <cuda_runtime.h>
#include <cuda_bf16.h>
#include <math.h>
#include <stdint.h>

#define B_ROWS 16384
#define TOK 16
#define TPB 256

// ---------------- gmem scratch ----------------
__device__ uint32_t g_xh[(size_t)TOK * B_ROWS * 64];   // [t][row][64] bf16x2 hi
__device__ uint32_t g_xl[(size_t)TOK * B_ROWS * 64];   // lo
__device__ uint32_t g_w1h[TOK * 512 * 64];             // bf16x2 hi [t][n][k/2]
__device__ uint32_t g_w1l[TOK * 512 * 64];
__device__ uint32_t g_w2h[TOK * 128 * 256];
__device__ uint32_t g_w2l[TOK * 128 * 256];
__device__ uint32_t g_w1h8[TOK * 16384];               // fp8 frag blobs per chunk (4KB)
__device__ uint32_t g_w1l8[TOK * 16384];               // lo*256
__device__ uint32_t g_w2h8[TOK * 16384];
__device__ uint32_t g_w2l8[TOK * 16384];
__device__ float    g_yp[(size_t)TOK * B_ROWS * 128];

// ---------------- helpers ----------------
__device__ __forceinline__ uint32_t smem_to_u32(const void* p) {
    uint32_t a;
    asm("{ .reg .u64 t; cvta.to.shared.u64 t, %1; cvt.u32.u64 %0, t; }" : "=r"(a) : "l"(p));
    return a;
}
__device__ __forceinline__ void ldsm4(uint32_t r[4], uint32_t addr) {
    asm volatile("ldmatrix.sync.aligned.m8n8.x4.shared.b16 {%0,%1,%2,%3}, [%4];"
                 : "=r"(r[0]), "=r"(r[1]), "=r"(r[2]), "=r"(r[3]) : "r"(addr));
}
__device__ __forceinline__ void mma_bf16(float c[4], const uint32_t a[4],
                                         uint32_t b0, uint32_t b1) {
    asm volatile(
        "mma.sync.aligned.m16n8k16.row.col.f32.bf16.bf16.f32 "
        "{%0,%1,%2,%3}, {%4,%5,%6,%7}, {%8,%9}, {%0,%1,%2,%3};"
        : "+f"(c[0]), "+f"(c[1]), "+f"(c[2]), "+f"(c[3])
        : "r"(a[0]), "r"(a[1]), "r"(a[2]), "r"(a[3]), "r"(b0), "r"(b1));
}
__device__ __forceinline__ void mma_fp8(float c[4], const uint32_t a[4],
                                        uint32_t b0, uint32_t b1) {
    asm volatile(
        "mma.sync.aligned.m16n8k32.row.col.f32.e4m3.e4m3.f32 "
        "{%0,%1,%2,%3}, {%4,%5,%6,%7}, {%8,%9}, {%0,%1,%2,%3};"
        : "+f"(c[0]), "+f"(c[1]), "+f"(c[2]), "+f"(c[3])
        : "r"(a[0]), "r"(a[1]), "r"(a[2]), "r"(a[3]), "r"(b0), "r"(b1));
}

#define CP_ASYNC16(dst, src) \
    asm volatile("cp.async.cg.shared.global [%0], [%1], 16;" :: "r"(dst), "l"(src))
#define CP_COMMIT() asm volatile("cp.async.commit_group;" ::: "memory")
#define CP_WAIT(n)  asm volatile("cp.async.wait_group %0;" :: "n"(n) : "memory")
#define STS32(a, v) asm volatile("st.shared.b32 [%0], %1;" :: "r"(a), "r"(v) : "memory")
#define STS16(a, v) asm volatile("st.shared.u16 [%0], %1;" :: "r"(a), "h"((unsigned short)(v)) : "memory")
#define LDS64(r0, r1, a) \
    asm volatile("ld.shared.v2.b32 {%0,%1}, [%2];" : "=r"(r0), "=r"(r1) : "r"(a))
#define LDS128(r0, r1, r2, r3, a) \
    asm volatile("ld.shared.v4.b32 {%0,%1,%2,%3}, [%4];" \
                 : "=r"(r0), "=r"(r1), "=r"(r2), "=r"(r3) : "r"(a))

__device__ __forceinline__ float bf_lo(uint32_t u) {
    return __bfloat162float(__ushort_as_bfloat16((unsigned short)(u & 0xFFFFu)));
}
__device__ __forceinline__ float bf_hi(uint32_t u) {
    return __bfloat162float(__ushort_as_bfloat16((unsigned short)(u >> 16)));
}
// d<7:0>=e4m3(b), d<15:8>=e4m3(a)
__device__ __forceinline__ uint32_t fp8x2(float a, float b) {
    unsigned short r;
    asm("cvt.rn.satfinite.e4m3x2.f32 %0, %1, %2;" : "=h"(r) : "f"(a), "f"(b));
    return (uint32_t)r;
}
__device__ __forceinline__ uint32_t fp8pack4(float f0, float f1, float f2, float f3) {
    return fp8x2(f1, f0) | (fp8x2(f3, f2) << 16);
}

__device__ __forceinline__ void split2(float f0, float f1, uint32_t& hh, uint32_t& ll) {
    __nv_bfloat16 h0 = __float2bfloat16(f0);
    __nv_bfloat16 h1 = __float2bfloat16(f1);
    float l0 = f0 - __bfloat162float(h0);
    float l1 = f1 - __bfloat162float(h1);
    __nv_bfloat16 m0 = __float2bfloat16(l0);
    __nv_bfloat16 m1 = __float2bfloat16(l1);
    hh = (uint32_t)__bfloat16_as_ushort(h0) | ((uint32_t)__bfloat16_as_ushort(h1) << 16);
    ll = (uint32_t)__bfloat16_as_ushort(m0) | ((uint32_t)__bfloat16_as_ushort(m1) << 16);
}
__device__ __forceinline__ float gelu_f(float x) {
    float z = 0.70710678118654752f * x;
    float r;
    if (fabsf(x) <= 2.0f) {
        float u = z * z;
        float p =              1.4807192e-8f;
        p = fmaf(p, u, -1.6365349e-7f);
        p = fmaf(p, u,  1.6462114e-6f);
        p = fmaf(p, u, -1.4925650e-5f);
        p = fmaf(p, u,  1.2055332e-4f);
        p = fmaf(p, u, -8.5483270e-4f);
        p = fmaf(p, u,  5.2239776e-3f);
        p = fmaf(p, u, -2.6866171e-2f);
        p = fmaf(p, u,  1.1283792e-1f);
        p = fmaf(p, u, -3.7612639e-1f);
        p = fmaf(p, u,  1.1283791671f);
        r = z * p;
    } else r = erff(z);
    return 0.5f * x * (1.0f + r);
}

// ---------------- aux kernels ----------------
__global__ void permute_x_split(const float* __restrict__ x) {
    __shared__ float s[128 * 17];
    const int row = blockIdx.x;
    const float* src = x + (size_t)row * 2048;
    for (int i = threadIdx.x; i < 2048; i += TPB) {
        int c = i >> 4, t = i & 15;
        s[c * 17 + t] = src[i];
    }
    __syncthreads();
    for (int i = threadIdx.x; i < 1024; i += TPB) {
        int t = i >> 6, cp = i & 63;
        uint32_t hh, ll;
        split2(s[(2 * cp) * 17 + t], s[(2 * cp + 1) * 17 + t], hh, ll);
        size_t o = ((size_t)t * B_ROWS + row) * 64 + cp;
        g_xh[o] = hh;
        g_xl[o] = ll;
    }
}

__global__ void permute_w1_split(const float* __restrict__ w) {
    int idx = blockIdx.x * TPB + threadIdx.x;
    const float* src = w + (size_t)idx * 2 * 16;
    float buf[32];
#pragma unroll
    for (int q = 0; q < 8; q++) {
        float4 v = *(const float4*)(src + q * 4);
        buf[q * 4 + 0] = v.x; buf[q * 4 + 1] = v.y;
        buf[q * 4 + 2] = v.z; buf[q * 4 + 3] = v.w;
    }
#pragma unroll
    for (int t = 0; t < TOK; t++) {
        uint32_t hh, ll;
        split2(buf[t], buf[16 + t], hh, ll);
        g_w1h[t * 32768 + idx] = hh;
        g_w1l[t * 32768 + idx] = ll;
    }
}
__global__ void permute_w2_split(const float* __restrict__ w) {
    int idx = blockIdx.x * TPB + threadIdx.x;
    const float* src = w + (size_t)idx * 2 * 16;
    float buf[32];
#pragma unroll
    for (int q = 0; q < 8; q++) {
        float4 v = *(const float4*)(src + q * 4);
        buf[q * 4 + 0] = v.x; buf[q * 4 + 1] = v.y;
        buf[q * 4 + 2] = v.z; buf[q * 4 + 3] = v.w;
    }
#pragma unroll
    for (int t = 0; t < TOK; t++) {
        uint32_t hh, ll;
        split2(buf[t], buf[16 + t], hh, ll);
        g_w2h[t * 32768 + idx] = hh;
        g_w2l[t * 32768 + idx] = ll;
    }
}

// fp8 fragment blobs, B-frag order: blob[(grpk)*32+lane] = {b0,b1} u32 pairs
__global__ void w1_f8_kernel() {
    int idx = blockIdx.x * TPB + threadIdx.x;   // [t][j16][ng4][ks4][lane32]
    int lane = idx & 31;
    int ks = (idx >> 5) & 3;
    int ng = (idx >> 7) & 3;
    int j  = (idx >> 9) & 15;
    int t  = idx >> 13;
    int n = j * 32 + ng * 8 + (lane >> 2);
    const uint32_t* sh = g_w1h + t * 32768 + n * 64;
    const uint32_t* sl = g_w1l + t * 32768 + n * 64;
    int o = t * 16384 + j * 1024 + ((ng * 4 + ks) * 32 + lane) * 2;
#pragma unroll
    for (int b = 0; b < 2; b++) {
        int kw = (ks * 32 + (lane & 3) * 4 + b * 16) >> 1;
        uint32_t hA = sh[kw], hB = sh[kw + 1];
        uint32_t lA = sl[kw], lB = sl[kw + 1];
        g_w1h8[o + b] = fp8pack4(bf_lo(hA), bf_hi(hA), bf_lo(hB), bf_hi(hB));
        g_w1l8[o + b] = fp8pack4(bf_lo(lA) * 256.f, bf_hi(lA) * 256.f,
                                 bf_lo(lB) * 256.f, bf_hi(lB) * 256.f);
    }
}
__global__ void w2_f8_kernel() {
    int idx = blockIdx.x * TPB + threadIdx.x;   // [t][j16][ng16][lane32]
    int lane = idx & 31;
    int ng = (idx >> 5) & 15;
    int j  = (idx >> 9) & 15;
    int t  = idx >> 13;
    int n = ng * 8 + (lane >> 2);
    const uint32_t* sh = g_w2h + t * 32768 + n * 256;
    const uint32_t* sl = g_w2l + t * 32768 + n * 256;
    int o = t * 16384 + j * 1024 + (ng * 32 + lane) * 2;
#pragma unroll
    for (int b = 0; b < 2; b++) {
        int kw = (j * 32 + (lane & 3) * 4 + b * 16) >> 1;
        uint32_t hA = sh[kw], hB = sh[kw + 1];
        uint32_t lA = sl[kw], lB = sl[kw + 1];
        g_w2h8[o + b] = fp8pack4(bf_lo(hA), bf_hi(hA), bf_lo(hB), bf_hi(hB));
        g_w2l8[o + b] = fp8pack4(bf_lo(lA) * 256.f, bf_hi(lA) * 256.f,
                                 bf_lo(lB) * 256.f, bf_hi(lB) * 256.f);
    }
}

__global__ void permute_y_kernel(float* __restrict__ y) {
    __shared__ float s[128 * 17];
    const int row = blockIdx.x;
    for (int i = threadIdx.x; i < 2048; i += TPB) {
        int t = i >> 7, o = i & 127;
        s[o * 17 + t] = g_yp[((size_t)t * B_ROWS + row) * 128 + o];
    }
    __syncthreads();
    float* dst = y + (size_t)row * 2048;
    for (int i = threadIdx.x; i < 2048; i += TPB) {
        int o = i >> 4, t = i & 15;
        dst[i] = s[o * 17 + t];
    }
}

// ---------------- main hybrid bf16+fp8 kernel ----------------
// M=64/CTA, chunk=32 (16). Warps 4 rowg x 2 colg. 2 CTAs/SM.
// smem: X 16K @0 (xh bf16, 64r x 256B, key r&7) [xl temp in W1 region]
//  W1 buf b (stride 16384): bf16h 8K (32r x 256B key r&7) | h8 4K @+8192 | l8 4K @+12288
//  W2 buf b (stride 18432): bf16h 10240 (128r x 80B) | h8 4K @+10240 | l8 4K @+14336
//  H: bf16 5120 (64r x 80B) | hh8 2K @+5120 | hl8 2K @+7168   (9216 total)
#define SM_X  0
#define SM_W1 16384
#define SM_W2 49152
#define W2STRIDE 18432
#define SM_H  86016
#define SM_TOTAL 95232

__device__ __forceinline__ void cpa_w1(uint32_t sb, int buf, int t, int j, int tid) {
    uint32_t base = sb + SM_W1 + buf * 16384;
    const uint4* h = (const uint4*)(g_w1h + (size_t)t * 32768 + (size_t)j * 32 * 64);
#pragma unroll
    for (int i = 0; i < 2; i++) {
        int lin = i * TPB + tid;
        int r = lin >> 4, c = lin & 15;
        CP_ASYNC16(base + r * 256 + ((c ^ (r & 7)) << 4), h + r * 16 + c);
    }
    CP_ASYNC16(base + 8192 + tid * 16, (const uint4*)(g_w1h8 + t * 16384 + j * 1024) + tid);
    CP_ASYNC16(base + 12288 + tid * 16, (const uint4*)(g_w1l8 + t * 16384 + j * 1024) + tid);
}
__device__ __forceinline__ void cpa_w2(uint32_t sb, int buf, int t, int j, int tid) {
    uint32_t base = sb + SM_W2 + buf * W2STRIDE;
    const uint4* h = (const uint4*)(g_w2h + (size_t)t * 32768);
#pragma unroll
    for (int i = 0; i < 2; i++) {
        int lin = i * TPB + tid;
        int r = lin >> 2, c = lin & 3;
        CP_ASYNC16(base + r * 80 + c * 16, h + r * 64 + j * 4 + c);
    }
    CP_ASYNC16(base + 10240 + tid * 16, (const uint4*)(g_w2h8 + t * 16384 + j * 1024) + tid);
    CP_ASYNC16(base + 14336 + tid * 16, (const uint4*)(g_w2l8 + t * 16384 + j * 1024) + tid);
}

__global__ void __launch_bounds__(TPB, 2) ffn_mma_kernel() {
    extern __shared__ char smem[];
    const uint32_t sb = smem_to_u32(smem);
    const int tid = threadIdx.x;
    const int lane = tid & 31;
    const int wid = tid >> 5;
    const int rowg = wid >> 1;
    const int colg = wid & 1;
    const int bid = blockIdx.x;
    const int t = bid >> 8;
    const int m0 = (bid & 255) * 64;

    const int rx = lane & 7;
    const int a_row16 = ((lane >> 3) & 1) * 8 + rx;
    const int a_cs = lane >> 4;
    const int b_row16 = ((lane >> 4) & 1) * 8 + rx;
    const int b_cs = (lane >> 3) & 1;
    const int g = lane >> 2, tt = lane & 3;

    const uint32_t aoffX = (uint32_t)(rowg * 16 + a_row16) * 256;
    const uint32_t aoffH = sb + SM_H + (uint32_t)(rowg * 16 + a_row16) * 80;
    const uint32_t boff1 = (uint32_t)(colg * 16 + b_row16) * 256;
    uint32_t boffg[4];
#pragma unroll
    for (int grp = 0; grp < 4; grp++)
        boffg[grp] = (uint32_t)(colg * 64 + grp * 16 + b_row16) * 80;

    // GELU store addrs (bf16 hi, pitch 80) and fp8 blob addrs
    uint32_t hstA[2][2], hb8[2][2];
#pragma unroll
    for (int n = 0; n < 2; n++) {
        int col = colg * 16 + n * 8 + 2 * tt;
        int r0 = rowg * 16 + g, r1 = r0 + 8;
        hstA[n][0] = sb + SM_H + (uint32_t)r0 * 80 + ((col >> 3) << 4) + (col & 7) * 2;
        hstA[n][1] = sb + SM_H + (uint32_t)r1 * 80 + ((col >> 3) << 4) + (col & 7) * 2;
        uint32_t laneB = (uint32_t)(g * 4 + n * 2 + (tt >> 1));
        uint32_t byo = (uint32_t)((tt & 1) * 2);
        hb8[n][0] = sb + SM_H + 5120 + rowg * 512 + laneB * 16 + (2 * colg) * 4 + byo;
        hb8[n][1] = hb8[n][0] + 4;   // q += 1 for row+8
    }
    const uint32_t h8ld = sb + SM_H + 5120 + rowg * 512 + lane * 16;

    // ---- prologue ----
    uint32_t xh8[4][4], xl8[4][4];
    {
        const uint4* xh = (const uint4*)(g_xh + ((size_t)t * B_ROWS + m0) * 64);
        const uint4* xl = (const uint4*)(g_xl + ((size_t)t * B_ROWS + m0) * 64);
#pragma unroll
        for (int i = 0; i < 4; i++) {
            int lin = i * TPB + tid;
            int r = lin >> 4, c = lin & 15;
            uint32_t off = (uint32_t)r * 256 + ((c ^ (r & 7)) << 4);
            CP_ASYNC16(sb + SM_X + off, xh + r * 16 + c);
            CP_ASYNC16(sb + SM_W1 + off, xl + r * 16 + c);
        }
        CP_COMMIT();
        CP_WAIT(0);
        __syncthreads();
        // build fp8 X fragments (a-frag order), lo scaled x256
        const int r0 = rowg * 16 + (lane >> 2);
#pragma unroll
        for (int ks = 0; ks < 4; ks++) {
#pragma unroll
            for (int q = 0; q < 4; q++) {
                int r = r0 + (q & 1) * 8;
                uint32_t off = (uint32_t)ks * 64 + (lane & 3) * 8 + (q >> 1) * 32;
                uint32_t ad = (uint32_t)r * 256 + ((((off >> 4)) ^ (r & 7)) << 4) + (off & 15);
                uint32_t w0, w1;
                LDS64(w0, w1, sb + SM_X + ad);
                xh8[ks][q] = fp8pack4(bf_lo(w0), bf_hi(w0), bf_lo(w1), bf_hi(w1));
                LDS64(w0, w1, sb + SM_W1 + ad);
                xl8[ks][q] = fp8pack4(bf_lo(w0) * 256.f, bf_hi(w0) * 256.f,
                                      bf_lo(w1) * 256.f, bf_hi(w1) * 256.f);
            }
        }
        __syncthreads();   // release W1 region
        cpa_w1(sb, 0, t, 0, tid);
        cpa_w2(sb, 0, t, 0, tid);
        CP_COMMIT();
        CP_WAIT(0);
        __syncthreads();
    }

    float c2[8][4];
#pragma unroll
    for (int n = 0; n < 8; n++)
#pragma unroll
        for (int q = 0; q < 4; q++) c2[n][q] = 0.0f;

    for (int j = 0; j < 16; j++) {
        const uint32_t w1b = sb + SM_W1 + (j & 1) * 16384;
        const uint32_t w2b = sb + SM_W2 + (j & 1) * W2STRIDE;

        if (j < 15) {
            cpa_w1(sb, (j + 1) & 1, t, j + 1, tid);
            cpa_w2(sb, (j + 1) & 1, t, j + 1, tid);
            CP_COMMIT();
        }

        // ---- GEMM1: bf16 hi + fp8 cross ----
        float c1[2][4];
#pragma unroll
        for (int n = 0; n < 2; n++)
#pragma unroll
            for (int q = 0; q < 4; q++) c1[n][q] = 0.0f;
#pragma unroll
        for (int k = 0; k < 8; k++) {
            uint32_t ah[4], bh[4];
            ldsm4(ah, sb + SM_X + aoffX + (uint32_t)(((2 * k + a_cs) ^ rx) << 4));
            ldsm4(bh, w1b + boff1 + (uint32_t)(((2 * k + b_cs) ^ rx) << 4));
            mma_bf16(c1[0], ah, bh[0], bh[1]);
            mma_bf16(c1[1], ah, bh[2], bh[3]);
        }
#pragma unroll
        for (int n = 0; n < 2; n++) {
            float cc[4] = {0.f, 0.f, 0.f, 0.f};
            int ng = colg * 2 + n;
#pragma unroll
            for (int ks = 0; ks < 4; ks++) {
                uint32_t off = (uint32_t)(((ng * 4 + ks) * 32 + lane) * 8);
                uint32_t l0, l1, h0, h1;
                LDS64(l0, l1, w1b + 12288 + off);
                LDS64(h0, h1, w1b + 8192 + off);
                mma_fp8(cc, xh8[ks], l0, l1);
                mma_fp8(cc, xl8[ks], h0, h1);
            }
#pragma unroll
            for (int q = 0; q < 4; q++)
                c1[n][q] = fmaf(cc[q], 0.00390625f, c1[n][q]);
        }

        // ---- GELU -> H (bf16 hi + fp8 v + fp8 resid*256) ----
#pragma unroll
        for (int n = 0; n < 2; n++) {
            float v0 = gelu_f(c1[n][0]), v1 = gelu_f(c1[n][1]);
            float v2 = gelu_f(c1[n][2]), v3 = gelu_f(c1[n][3]);
            __nv_bfloat16 b0 = __float2bfloat16(v0), b1 = __float2bfloat16(v1);
            __nv_bfloat16 b2 = __float2bfloat16(v2), b3 = __float2bfloat16(v3);
            STS32(hstA[n][0], (uint32_t)__bfloat16_as_ushort(b0) |
                              ((uint32_t)__bfloat16_as_ushort(b1) << 16));
            STS32(hstA[n][1], (uint32_t)__bfloat16_as_ushort(b2) |
                              ((uint32_t)__bfloat16_as_ushort(b3) << 16));
            STS16(hb8[n][0], fp8x2(v1, v0));
            STS16(hb8[n][1], fp8x2(v3, v2));
            float e0 = (v0 - __bfloat162float(b0)) * 256.f;
            float e1 = (v1 - __bfloat162float(b1)) * 256.f;
            float e2 = (v2 - __bfloat162float(b2)) * 256.f;
            float e3 = (v3 - __bfloat162float(b3)) * 256.f;
            STS16(hb8[n][0] + 2048, fp8x2(e1, e0));
            STS16(hb8[n][1] + 2048, fp8x2(e3, e2));
        }
        __syncthreads();   // H visible

        // ---- GEMM2: bf16 hi + fp8 cross ----
#pragma unroll
        for (int k = 0; k < 2; k++) {
            uint32_t ah[4];
            ldsm4(ah, aoffH + (uint32_t)(((2 * k + a_cs)) << 4));
#pragma unroll
            for (int grp = 0; grp < 4; grp++) {
                uint32_t bh[4];
                ldsm4(bh, w2b + boffg[grp] + (uint32_t)(((2 * k + b_cs)) << 4));
                mma_bf16(c2[grp * 2], ah, bh[0], bh[1]);
                mma_bf16(c2[grp * 2 + 1], ah, bh[2], bh[3]);
            }
        }
        {
            uint32_t ah8[4], al8[4];
            LDS128(ah8[0], ah8[1], ah8[2], ah8[3], h8ld);
            LDS128(al8[0], al8[1], al8[2], al8[3], h8ld + 2048);
#pragma unroll
            for (int n = 0; n < 8; n++) {
                int ng = colg * 8 + n;
                uint32_t off = (uint32_t)((ng * 32 + lane) * 8);
                uint32_t l0, l1, h0, h1;
                LDS64(l0, l1, w2b + 14336 + off);
                LDS64(h0, h1, w2b + 10240 + off);
                float cc[4] = {0.f, 0.f, 0.f, 0.f};
                mma_fp8(cc, ah8, l0, l1);
                mma_fp8(cc, al8, h0, h1);
#pragma unroll
                for (int q = 0; q < 4; q++)
                    c2[n][q] = fmaf(cc[q], 0.00390625f, c2[n][q]);
            }
        }

        if (j < 15) {
            CP_WAIT(0);
            __syncthreads();   // next W bufs ready; H free
        }
    }

    // ---- store C2 -> g_yp ----
    {
        float* ybase = g_yp + ((size_t)t * B_ROWS + m0 + rowg * 16) * 128;
#pragma unroll
        for (int n = 0; n < 8; n++) {
            int col = colg * 64 + n * 8 + 2 * tt;
            *(float2*)(ybase + (size_t)g * 128 + col) = make_float2(c2[n][0], c2[n][1]);
            *(float2*)(ybase + (size_t)(g + 8) * 128 + col) = make_float2(c2[n][2], c2[n][3]);
        }
    }
}

// ---------------- launch ----------------
extern "C" void kernel_launch(void* const* d_in, const int* in_sizes, int n_in,
                              void* d_out, int out_size) {
    const float* x  = (const float*)d_in[0];
    const float* w1 = (const float*)d_in[1];
    const float* w2 = (const float*)d_in[2];
    float* y = (float*)d_out;
    (void)in_sizes; (void)n_in; (void)out_size;

    cudaFuncSetAttribute(ffn_mma_kernel,
                         cudaFuncAttributeMaxDynamicSharedMemorySize, SM_TOTAL);

    permute_x_split<<<B_ROWS, TPB>>>(x);
    permute_w1_split<<<(512 * 64) / TPB, TPB>>>(w1);
    permute_w2_split<<<(128 * 256) / TPB, TPB>>>(w2);
    w1_f8_kernel<<<512, TPB>>>();
    w2_f8_kernel<<<512, TPB>>>();
    ffn_mma_kernel<<<TOK * (B_ROWS / 64), TPB, SM_TOTAL>>>();
    permute_y_kernel<<<B_ROWS, TPB>>>(y);
}